// round 1
// baseline (speedup 1.0000x reference)
#include <cuda_runtime.h>

#define IN_DIM   8192
#define OUT_DIM  16384
#define TOP_K    327

// scratch (no allocations allowed)
__device__ int g_rows[IN_DIM];
__device__ int g_nrows;
__device__ int g_overlap[OUT_DIM];

// ---------------------------------------------------------------------------
// k_init: zero overlap accumulator + active-row counter
// ---------------------------------------------------------------------------
__global__ void k_init() {
    int j = blockIdx.x * blockDim.x + threadIdx.x;
    if (j < OUT_DIM) g_overlap[j] = 0;
    if (j == 0) g_nrows = 0;
}

// ---------------------------------------------------------------------------
// k_compact: build compact list of active rows (order irrelevant for the sum)
// ---------------------------------------------------------------------------
__global__ void k_compact(const int* __restrict__ x) {
    int i = blockIdx.x * blockDim.x + threadIdx.x;
    if (i < IN_DIM && x[i] != 0) {
        int pos = atomicAdd(&g_nrows, 1);
        g_rows[pos] = i;
    }
}

// ---------------------------------------------------------------------------
// k_gemv: overlap[c] += sum over active rows of (p[row][c] > 0.5f)
//   grid = (COL_TILES, ROW_CHUNKS), block = 256 threads, 4 cols/thread (float4)
// ---------------------------------------------------------------------------
#define GEMV_TB        256
#define COLS_PER_BLK   (GEMV_TB * 4)          // 1024
#define COL_TILES      (OUT_DIM / COLS_PER_BLK) // 16
#define ROW_CHUNKS     32
#define MAX_CHUNK      ((IN_DIM + ROW_CHUNKS - 1) / ROW_CHUNKS) // 256

__global__ __launch_bounds__(GEMV_TB) void k_gemv(const float* __restrict__ p) {
    __shared__ int srows[MAX_CHUNK];

    const int nact  = g_nrows;
    const int chunk = (nact + ROW_CHUNKS - 1) / ROW_CHUNKS;
    const int r0    = blockIdx.y * chunk;
    const int r1    = min(r0 + chunk, nact);
    const int nr    = r1 - r0;
    if (nr <= 0) return;

    // stage row ids for this chunk into shared
    for (int r = threadIdx.x; r < nr; r += GEMV_TB)
        srows[r] = g_rows[r0 + r];
    __syncthreads();

    const int col4 = blockIdx.x * (COLS_PER_BLK / 4) + threadIdx.x; // float4 index
    const float4* __restrict__ p4 = (const float4*)p;
    const long stride4 = OUT_DIM / 4;

    int c0 = 0, c1 = 0, c2 = 0, c3 = 0;

    int r = 0;
    #pragma unroll 1
    for (; r + 8 <= nr; r += 8) {
        #pragma unroll
        for (int u = 0; u < 8; u++) {
            const int row = srows[r + u];
            const float4 v = __ldg(&p4[(long)row * stride4 + col4]);
            c0 += (v.x > 0.5f);
            c1 += (v.y > 0.5f);
            c2 += (v.z > 0.5f);
            c3 += (v.w > 0.5f);
        }
    }
    for (; r < nr; r++) {
        const int row = srows[r];
        const float4 v = __ldg(&p4[(long)row * stride4 + col4]);
        c0 += (v.x > 0.5f);
        c1 += (v.y > 0.5f);
        c2 += (v.z > 0.5f);
        c3 += (v.w > 0.5f);
    }

    const int cbase = col4 * 4;
    atomicAdd(&g_overlap[cbase + 0], c0);
    atomicAdd(&g_overlap[cbase + 1], c1);
    atomicAdd(&g_overlap[cbase + 2], c2);
    atomicAdd(&g_overlap[cbase + 3], c3);
}

// ---------------------------------------------------------------------------
// k_topk: single block. Histogram over overlap values (0..8192), find the
// k-th largest value T via top-down 3-level scan, then emit 0/1 output with
// jax.lax.top_k tie-breaking (lowest index wins among values == T).
// ---------------------------------------------------------------------------
#define TK_THREADS 1024
#define NBINS      (IN_DIM + 1)   // 8193
#define SEG        (OUT_DIM / TK_THREADS) // 16

__global__ __launch_bounds__(TK_THREADS) void k_topk(float* __restrict__ out) {
    __shared__ int hist[NBINS];
    __shared__ int coarse[TK_THREADS];   // sums of 8 hist bins
    __shared__ int sup[32];              // sums of 32 coarse bins
    __shared__ int scan[TK_THREADS];
    __shared__ int s_T, s_rem;

    const int t = threadIdx.x;

    for (int b = t; b < NBINS; b += TK_THREADS) hist[b] = 0;
    __syncthreads();

    for (int j = t; j < OUT_DIM; j += TK_THREADS)
        atomicAdd(&hist[g_overlap[j]], 1);
    __syncthreads();

    // level 1: 1024 coarse bins of 8
    {
        int c = 0;
        #pragma unroll
        for (int b = 0; b < 8; b++) c += hist[t * 8 + b];
        coarse[t] = c;
    }
    __syncthreads();

    // level 2: 32 super bins of 32 coarse
    if (t < 32) {
        int s = 0;
        #pragma unroll
        for (int b = 0; b < 32; b++) s += coarse[t * 32 + b];
        sup[t] = s;
    }
    __syncthreads();

    // threshold search (top-down), single thread (~72 serial iterations)
    if (t == 0) {
        int cum = 0;
        int si = 31;
        for (; si > 0; si--) {
            if (cum + sup[si] >= TOP_K) break;
            cum += sup[si];
        }
        int ci = si * 32 + 31;
        for (; ci > 0; ci--) {
            if (cum + coarse[ci] >= TOP_K) break;
            cum += coarse[ci];
        }
        int bi = ci * 8 + 7;
        for (; bi > 0; bi--) {
            if (cum + hist[bi] >= TOP_K) break;
            cum += hist[bi];
        }
        s_T   = bi;            // k-th largest value
        s_rem = TOP_K - cum;   // #ties at T to accept (cum == count of values > T)
    }
    __syncthreads();

    const int T   = s_T;
    const int rem = s_rem;

    // tie ranking by ascending index: thread t owns cols [t*SEG, (t+1)*SEG)
    const int base = t * SEG;
    int ov[SEG];
    int cnt = 0;
    #pragma unroll
    for (int j = 0; j < SEG; j++) {
        ov[j] = g_overlap[base + j];
        cnt += (ov[j] == T);
    }
    scan[t] = cnt;
    __syncthreads();

    // Hillis-Steele inclusive scan over 1024 thread tie-counts
    for (int off = 1; off < TK_THREADS; off <<= 1) {
        int add = (t >= off) ? scan[t - off] : 0;
        __syncthreads();
        scan[t] += add;
        __syncthreads();
    }
    int run = scan[t] - cnt;  // exclusive prefix = global tie rank of first tie in my segment

    #pragma unroll
    for (int j = 0; j < SEG; j++) {
        float o;
        if (ov[j] > T) {
            o = 1.0f;
        } else if (ov[j] == T) {
            o = (run < rem) ? 1.0f : 0.0f;
            run++;
        } else {
            o = 0.0f;
        }
        out[base + j] = o;
    }
}

// ---------------------------------------------------------------------------
extern "C" void kernel_launch(void* const* d_in, const int* in_sizes, int n_in,
                              void* d_out, int out_size) {
    const int*   x = (const int*)d_in[0];   // [1, 8192] int32
    const float* p = (const float*)d_in[1]; // [8192, 16384] float32
    float* out = (float*)d_out;             // [1, 16384] float32

    k_init<<<(OUT_DIM + 255) / 256, 256>>>();
    k_compact<<<(IN_DIM + 255) / 256, 256>>>(x);
    dim3 grid(COL_TILES, ROW_CHUNKS);
    k_gemv<<<grid, GEMV_TB>>>(p);
    k_topk<<<1, TK_THREADS>>>(out);
}

// round 2
// speedup vs baseline: 1.0988x; 1.0988x over previous
#include <cuda_runtime.h>

#define IN_DIM   8192
#define OUT_DIM  16384
#define TOP_K    327

// scratch (no allocations allowed)
__device__ int g_rows[IN_DIM];
__device__ int g_nrows;
__device__ int g_overlap[OUT_DIM];

// ---------------------------------------------------------------------------
// k_prep: block 0 compacts active rows; blocks 1..16 zero the overlap array.
// grid = 17 blocks x 1024 threads
// ---------------------------------------------------------------------------
__global__ __launch_bounds__(1024) void k_prep(const int* __restrict__ x) {
    if (blockIdx.x == 0) {
        __shared__ int s_cnt;
        if (threadIdx.x == 0) s_cnt = 0;
        __syncthreads();
        for (int i = threadIdx.x; i < IN_DIM; i += 1024) {
            if (x[i] != 0) {
                int pos = atomicAdd(&s_cnt, 1);
                g_rows[pos] = i;
            }
        }
        __syncthreads();
        if (threadIdx.x == 0) g_nrows = s_cnt;
    } else {
        int j = (blockIdx.x - 1) * 1024 + threadIdx.x;
        g_overlap[j] = 0;
    }
}

// ---------------------------------------------------------------------------
// k_gemv: overlap[c] += sum over active rows of (p[row][c] > 0.5f)
//   grid = (COL_TILES, ROW_CHUNKS), block = 256 threads, 4 cols/thread (float4)
//   This kernel runs at the LTS/HBM bandwidth ceiling (~256MB of p traffic).
// ---------------------------------------------------------------------------
#define GEMV_TB        256
#define COLS_PER_BLK   (GEMV_TB * 4)            // 1024
#define COL_TILES      (OUT_DIM / COLS_PER_BLK) // 16
#define ROW_CHUNKS     32
#define MAX_CHUNK      ((IN_DIM + ROW_CHUNKS - 1) / ROW_CHUNKS) // 256

__global__ __launch_bounds__(GEMV_TB) void k_gemv(const float* __restrict__ p) {
    __shared__ int srows[MAX_CHUNK];

    const int nact  = g_nrows;
    const int chunk = (nact + ROW_CHUNKS - 1) / ROW_CHUNKS;
    const int r0    = blockIdx.y * chunk;
    const int r1    = min(r0 + chunk, nact);
    const int nr    = r1 - r0;
    if (nr <= 0) return;

    for (int r = threadIdx.x; r < nr; r += GEMV_TB)
        srows[r] = g_rows[r0 + r];
    __syncthreads();

    const int col4 = blockIdx.x * (COLS_PER_BLK / 4) + threadIdx.x;
    const float4* __restrict__ p4 = (const float4*)p;
    const long stride4 = OUT_DIM / 4;

    int c0 = 0, c1 = 0, c2 = 0, c3 = 0;

    int r = 0;
    #pragma unroll 1
    for (; r + 8 <= nr; r += 8) {
        #pragma unroll
        for (int u = 0; u < 8; u++) {
            const int row = srows[r + u];
            const float4 v = __ldg(&p4[(long)row * stride4 + col4]);
            c0 += (v.x > 0.5f);
            c1 += (v.y > 0.5f);
            c2 += (v.z > 0.5f);
            c3 += (v.w > 0.5f);
        }
    }
    for (; r < nr; r++) {
        const int row = srows[r];
        const float4 v = __ldg(&p4[(long)row * stride4 + col4]);
        c0 += (v.x > 0.5f);
        c1 += (v.y > 0.5f);
        c2 += (v.z > 0.5f);
        c3 += (v.w > 0.5f);
    }

    const int cbase = col4 * 4;
    atomicAdd(&g_overlap[cbase + 0], c0);
    atomicAdd(&g_overlap[cbase + 1], c1);
    atomicAdd(&g_overlap[cbase + 2], c2);
    atomicAdd(&g_overlap[cbase + 3], c3);
}

// ---------------------------------------------------------------------------
// k_topk: single block, 1024 threads. Each thread holds 16 overlap values in
// registers. Binary search (13 iters) for the k-th largest value T via
// cooperative count(>= mid); then tie-break by ascending index using a
// shfl-based block prefix scan. No shared-memory atomics anywhere.
// ---------------------------------------------------------------------------
#define TK_THREADS 1024
#define SEG        (OUT_DIM / TK_THREADS) // 16

__global__ __launch_bounds__(TK_THREADS) void k_topk(float* __restrict__ out) {
    __shared__ int s_warp[32];
    __shared__ int s_bc;

    const int t    = threadIdx.x;
    const int lane = t & 31;
    const int wid  = t >> 5;
    const int base = t * SEG;

    // load my 16 contiguous overlap values into registers (int4 vectorized)
    int ov[SEG];
    const int4* g4 = (const int4*)(g_overlap + base);
    #pragma unroll
    for (int j = 0; j < SEG / 4; j++) {
        int4 v = g4[j];
        ov[4 * j + 0] = v.x;
        ov[4 * j + 1] = v.y;
        ov[4 * j + 2] = v.z;
        ov[4 * j + 3] = v.w;
    }

    // cooperative count of values >= m across the whole block
    auto count_ge = [&](int m) -> int {
        int c = 0;
        #pragma unroll
        for (int j = 0; j < SEG; j++) c += (ov[j] >= m);
        #pragma unroll
        for (int o = 16; o; o >>= 1)
            c += __shfl_xor_sync(0xffffffffu, c, o);
        if (lane == 0) s_warp[wid] = c;
        __syncthreads();
        if (wid == 0) {
            int v = s_warp[lane];
            #pragma unroll
            for (int o = 16; o; o >>= 1)
                v += __shfl_xor_sync(0xffffffffu, v, o);
            if (lane == 0) s_bc = v;
        }
        __syncthreads();
        int r = s_bc;
        __syncthreads();  // protect s_warp/s_bc before reuse
        return r;
    };

    // binary search: largest T with count(>= T) >= TOP_K
    int lo = 0, hi = IN_DIM;
    while (lo < hi) {
        int mid = (lo + hi + 1) >> 1;
        if (count_ge(mid) >= TOP_K) lo = mid;
        else                        hi = mid - 1;
    }
    const int T   = lo;
    const int rem = TOP_K - count_ge(T + 1);  // ties at T to accept (lowest index)

    // tie ranking: exclusive prefix of tie-counts in index order
    int cnt = 0;
    #pragma unroll
    for (int j = 0; j < SEG; j++) cnt += (ov[j] == T);

    int inc = cnt;  // warp-inclusive scan
    #pragma unroll
    for (int o = 1; o < 32; o <<= 1) {
        int n = __shfl_up_sync(0xffffffffu, inc, o);
        if (lane >= o) inc += n;
    }
    if (lane == 31) s_warp[wid] = inc;  // warp totals
    __syncthreads();
    if (wid == 0) {
        int tot = s_warp[lane];
        int v = tot;
        #pragma unroll
        for (int o = 1; o < 32; o <<= 1) {
            int n = __shfl_up_sync(0xffffffffu, v, o);
            if (lane >= o) v += n;
        }
        s_warp[lane] = v - tot;  // exclusive warp offsets
    }
    __syncthreads();
    int run = s_warp[wid] + (inc - cnt);  // global tie rank of my first tie

    // emit 0/1 output, float4 stores
    float4* o4 = (float4*)(out + base);
    #pragma unroll
    for (int j = 0; j < SEG / 4; j++) {
        float r[4];
        #pragma unroll
        for (int q = 0; q < 4; q++) {
            int v = ov[4 * j + q];
            float o;
            if (v > T) {
                o = 1.0f;
            } else if (v == T) {
                o = (run < rem) ? 1.0f : 0.0f;
                run++;
            } else {
                o = 0.0f;
            }
            r[q] = o;
        }
        o4[j] = make_float4(r[0], r[1], r[2], r[3]);
    }
}

// ---------------------------------------------------------------------------
extern "C" void kernel_launch(void* const* d_in, const int* in_sizes, int n_in,
                              void* d_out, int out_size) {
    const int*   x = (const int*)d_in[0];   // [1, 8192] int32
    const float* p = (const float*)d_in[1]; // [8192, 16384] float32
    float* out = (float*)d_out;             // [1, 16384] float32

    k_prep<<<17, 1024>>>(x);
    dim3 grid(COL_TILES, ROW_CHUNKS);
    k_gemv<<<grid, GEMV_TB>>>(p);
    k_topk<<<1, TK_THREADS>>>(out);
}

// round 5
// speedup vs baseline: 1.1289x; 1.0273x over previous
#include <cuda_runtime.h>

#define IN_DIM   8192
#define OUT_DIM  16384
#define TOP_K    327

// scratch (no allocations allowed)
__device__ int g_overlap[OUT_DIM];

// ---------------------------------------------------------------------------
// k_zero: zero the overlap accumulator. 4 blocks x 1024 threads x 1 int4.
// ---------------------------------------------------------------------------
__global__ __launch_bounds__(1024) void k_zero() {
    int j = blockIdx.x * 1024 + threadIdx.x;
    ((int4*)g_overlap)[j] = make_int4(0, 0, 0, 0);
}

// ---------------------------------------------------------------------------
// k_gemv: overlap[c] += sum over active rows of (p[row][c] > 0.5f)
//   grid = (COL_TILES=16, ROW_STRIPS=64), block = 256 threads.
//   Each block owns a 128-row strip of the ORIGINAL row space and compacts
//   the active rows locally via warp ballot (x is tiny and L2-resident),
//   skipping ~50% of p's rows. Each thread handles 4 cols (one float4).
//   This kernel is DRAM/LTS-bandwidth-bound (~256 MB effective traffic).
// ---------------------------------------------------------------------------
#define GEMV_TB     256
#define STRIP       128                     // original rows per block
#define ROW_STRIPS  (IN_DIM / STRIP)        // 64
#define COLS_BLK    (GEMV_TB * 4)           // 1024
#define COL_TILES   (OUT_DIM / COLS_BLK)    // 16

__global__ __launch_bounds__(GEMV_TB) void k_gemv(const int* __restrict__ x,
                                                  const float* __restrict__ p) {
    __shared__ int srows[STRIP];
    __shared__ int s_wcnt[4];

    const int t    = threadIdx.x;
    const int lane = t & 31;
    const int w    = t >> 5;
    const int r0   = blockIdx.y * STRIP;

    // --- local compaction of this block's 128-row strip (warps 0-3) ---
    int a = 0, myrow = 0;
    unsigned m = 0;
    if (w < 4) {
        myrow = r0 + t;
        a = (x[myrow] != 0);
        m = __ballot_sync(0xffffffffu, a);
        if (lane == 0) s_wcnt[w] = __popc(m);
    }
    __syncthreads();
    const int nr = s_wcnt[0] + s_wcnt[1] + s_wcnt[2] + s_wcnt[3];
    if (w < 4 && a) {
        int off = 0;
        #pragma unroll
        for (int i = 0; i < 4; i++) if (i < w) off += s_wcnt[i];
        int rank = __popc(m & ((1u << lane) - 1u));
        srows[off + rank] = myrow;
    }
    __syncthreads();
    if (nr == 0) return;

    // --- binarized accumulation over active rows ---
    const int col4 = blockIdx.x * (COLS_BLK / 4) + t;   // float4 index
    const float4* __restrict__ p4 = (const float4*)p;
    const long stride4 = OUT_DIM / 4;

    int c0 = 0, c1 = 0, c2 = 0, c3 = 0;

    int r = 0;
    #pragma unroll 1
    for (; r + 8 <= nr; r += 8) {
        #pragma unroll
        for (int u = 0; u < 8; u++) {
            const int row = srows[r + u];
            const float4 v = __ldg(&p4[(long)row * stride4 + col4]);
            c0 += (v.x > 0.5f);
            c1 += (v.y > 0.5f);
            c2 += (v.z > 0.5f);
            c3 += (v.w > 0.5f);
        }
    }
    for (; r < nr; r++) {
        const int row = srows[r];
        const float4 v = __ldg(&p4[(long)row * stride4 + col4]);
        c0 += (v.x > 0.5f);
        c1 += (v.y > 0.5f);
        c2 += (v.z > 0.5f);
        c3 += (v.w > 0.5f);
    }

    const int cbase = col4 * 4;
    atomicAdd(&g_overlap[cbase + 0], c0);
    atomicAdd(&g_overlap[cbase + 1], c1);
    atomicAdd(&g_overlap[cbase + 2], c2);
    atomicAdd(&g_overlap[cbase + 3], c3);
}

// ---------------------------------------------------------------------------
// k_topk: single block, 1024 threads. Register-resident binary search for the
// k-th largest value T, then jax.lax.top_k tie-break (lowest index wins).
// ---------------------------------------------------------------------------
#define TK_THREADS 1024
#define SEG        (OUT_DIM / TK_THREADS) // 16

__global__ __launch_bounds__(TK_THREADS) void k_topk(float* __restrict__ out) {
    __shared__ int s_warp[32];
    __shared__ int s_bc;

    const int t    = threadIdx.x;
    const int lane = t & 31;
    const int wid  = t >> 5;
    const int base = t * SEG;

    int ov[SEG];
    const int4* g4 = (const int4*)(g_overlap + base);
    #pragma unroll
    for (int j = 0; j < SEG / 4; j++) {
        int4 v = g4[j];
        ov[4 * j + 0] = v.x;
        ov[4 * j + 1] = v.y;
        ov[4 * j + 2] = v.z;
        ov[4 * j + 3] = v.w;
    }

    auto count_ge = [&](int m) -> int {
        int c = 0;
        #pragma unroll
        for (int j = 0; j < SEG; j++) c += (ov[j] >= m);
        #pragma unroll
        for (int o = 16; o; o >>= 1)
            c += __shfl_xor_sync(0xffffffffu, c, o);
        if (lane == 0) s_warp[wid] = c;
        __syncthreads();
        if (wid == 0) {
            int v = s_warp[lane];
            #pragma unroll
            for (int o = 16; o; o >>= 1)
                v += __shfl_xor_sync(0xffffffffu, v, o);
            if (lane == 0) s_bc = v;
        }
        __syncthreads();
        int r = s_bc;
        __syncthreads();
        return r;
    };

    // binary search: largest T with count(>= T) >= TOP_K
    int lo = 0, hi = IN_DIM;
    while (lo < hi) {
        int mid = (lo + hi + 1) >> 1;
        if (count_ge(mid) >= TOP_K) lo = mid;
        else                        hi = mid - 1;
    }
    const int T   = lo;
    const int rem = TOP_K - count_ge(T + 1);  // ties at T to accept (lowest index)

    // tie ranking: exclusive prefix of tie-counts in index order
    int cnt = 0;
    #pragma unroll
    for (int j = 0; j < SEG; j++) cnt += (ov[j] == T);

    int inc = cnt;
    #pragma unroll
    for (int o = 1; o < 32; o <<= 1) {
        int n = __shfl_up_sync(0xffffffffu, inc, o);
        if (lane >= o) inc += n;
    }
    if (lane == 31) s_warp[wid] = inc;
    __syncthreads();
    if (wid == 0) {
        int tot = s_warp[lane];
        int v = tot;
        #pragma unroll
        for (int o = 1; o < 32; o <<= 1) {
            int n = __shfl_up_sync(0xffffffffu, v, o);
            if (lane >= o) v += n;
        }
        s_warp[lane] = v - tot;
    }
    __syncthreads();
    int run = s_warp[wid] + (inc - cnt);

    float4* o4 = (float4*)(out + base);
    #pragma unroll
    for (int j = 0; j < SEG / 4; j++) {
        float r[4];
        #pragma unroll
        for (int q = 0; q < 4; q++) {
            int v = ov[4 * j + q];
            float o;
            if (v > T) {
                o = 1.0f;
            } else if (v == T) {
                o = (run < rem) ? 1.0f : 0.0f;
                run++;
            } else {
                o = 0.0f;
            }
            r[q] = o;
        }
        o4[j] = make_float4(r[0], r[1], r[2], r[3]);
    }
}

// ---------------------------------------------------------------------------
extern "C" void kernel_launch(void* const* d_in, const int* in_sizes, int n_in,
                              void* d_out, int out_size) {
    const int*   x = (const int*)d_in[0];   // [1, 8192] int32
    const float* p = (const float*)d_in[1]; // [8192, 16384] float32
    float* out = (float*)d_out;             // [1, 16384] float32

    k_zero<<<OUT_DIM / 4 / 1024, 1024>>>();
    dim3 grid(COL_TILES, ROW_STRIPS);
    k_gemv<<<grid, GEMV_TB>>>(x, p);
    k_topk<<<1, TK_THREADS>>>(out);
}